// round 1
// baseline (speedup 1.0000x reference)
#include <cuda_runtime.h>
#include <math.h>
#include <float.h>

#define NPTS  8192
#define NDOWN 2048
#define KNN   16

// ----------------------------------------------------------------------------
// Scratch (no cudaMalloc allowed) — one big float arena + int arena.
// ----------------------------------------------------------------------------
__device__ float g_f[37600000];
__device__ int   g_i[700000];

// float offsets
static const size_t O_A1  = 0;                          // 8192*64
static const size_t O_B1  = O_A1  + (size_t)8192*64;
static const size_t O_X1  = O_B1  + (size_t)8192*64;
static const size_t O_A2  = O_X1  + (size_t)8192*64;    // 8192*128
static const size_t O_B2  = O_A2  + (size_t)8192*128;
static const size_t O_X2  = O_B2  + (size_t)8192*128;
static const size_t O_Q1  = O_X2  + (size_t)8192*128;   // 8192*256
static const size_t O_K1  = O_Q1  + (size_t)8192*256;
static const size_t O_V1  = O_K1  + (size_t)8192*256;
static const size_t O_X3  = O_V1  + (size_t)8192*256;
static const size_t O_Q2  = O_X3  + (size_t)8192*256;   // 8192*512
static const size_t O_K2  = O_Q2  + (size_t)8192*512;
static const size_t O_V2  = O_K2  + (size_t)8192*512;
static const size_t O_X4  = O_V2  + (size_t)8192*512;
static const size_t O_PX  = O_X4  + (size_t)8192*512;
static const size_t O_PM  = O_PX  + (size_t)8192*512;   // 2048*512
static const size_t O_XD  = O_PM  + (size_t)2048*512;
static const size_t O_XU  = O_XD  + (size_t)2048*512;   // 2048*256
static const size_t O_H   = O_XU  + (size_t)2048*256;   // 2048*128
static const size_t O_GS  = O_H   + (size_t)2048*128;   // 512
static const size_t O_BE  = O_GS  + 512;                // 256
static const size_t O_B2E = O_BE  + 256;                // 128
static const size_t O_WD1 = O_B2E + 128;                // 3*64
static const size_t O_WD2 = O_WD1 + 192;                // 64*128
static const size_t O_P4  = O_WD2 + 8192;               // 8192*4 (float4-aligned)
static const size_t O_S1D = O_P4  + (size_t)8192*4;     // 8192*64

// int offsets
static const size_t OI_IDX  = 0;                        // 8192*16
static const size_t OI_IDXD = (size_t)8192*16;          // 2048*16
static const size_t OI_S1I  = OI_IDXD + (size_t)2048*16;// 8192*64

// ----------------------------------------------------------------------------
// kNN
// ----------------------------------------------------------------------------
__device__ __forceinline__ void topk_insert(float s, int j, float (&d)[KNN], int (&id)[KNN]) {
    if (s < d[KNN - 1]) {
        d[KNN - 1] = s; id[KNN - 1] = j;
#pragma unroll
        for (int t = KNN - 1; t > 0; --t) {
            if (d[t] < d[t - 1]) {
                float td = d[t]; d[t] = d[t - 1]; d[t - 1] = td;
                int   ti = id[t]; id[t] = id[t - 1]; id[t - 1] = ti;
            }
        }
    }
}

__global__ void prep_p4_kernel(const float* __restrict__ p, float4* __restrict__ p4) {
    int i = blockIdx.x * blockDim.x + threadIdx.x;
    if (i < NPTS) {
        float x = p[3 * i], y = p[3 * i + 1], z = p[3 * i + 2];
        p4[i] = make_float4(x, y, z, x * x + y * y + z * z);
    }
}

// grid: (nq/128, 4)  block: 128.  score = |pj|^2 - 2 q.pj  (same ranking as d2)
__global__ void knn_stage1_kernel(const float4* __restrict__ p4, int qstride,
                                  float* __restrict__ s1d, int* __restrict__ s1i) {
    const int CH = NPTS / 4;  // 2048 candidates per chunk
    int q = blockIdx.x * blockDim.x + threadIdx.x;
    int chunk = blockIdx.y;
    int c0 = chunk * CH;

    float4 qp = p4[q * qstride];
    float qx = -2.f * qp.x, qy = -2.f * qp.y, qz = -2.f * qp.z;

    float d[KNN]; int id[KNN];
#pragma unroll
    for (int t = 0; t < KNN; ++t) { d[t] = FLT_MAX; id[t] = 0; }

    __shared__ float4 tile[512];
    for (int t0 = 0; t0 < CH; t0 += 512) {
        __syncthreads();
        for (int i = threadIdx.x; i < 512; i += blockDim.x)
            tile[i] = p4[c0 + t0 + i];
        __syncthreads();
#pragma unroll 4
        for (int i = 0; i < 512; ++i) {
            float4 c = tile[i];
            float s = fmaf(qx, c.x, fmaf(qy, c.y, fmaf(qz, c.z, c.w)));
            topk_insert(s, c0 + t0 + i, d, id);
        }
    }
    size_t o = ((size_t)q * 4 + chunk) * KNN;
#pragma unroll
    for (int t = 0; t < KNN; ++t) { s1d[o + t] = d[t]; s1i[o + t] = id[t]; }
}

__global__ void knn_stage2_kernel(const float* __restrict__ s1d, const int* __restrict__ s1i,
                                  int nq, int* __restrict__ outidx) {
    int q = blockIdx.x * blockDim.x + threadIdx.x;
    if (q >= nq) return;
    float d[KNN]; int id[KNN];
#pragma unroll
    for (int t = 0; t < KNN; ++t) { d[t] = FLT_MAX; id[t] = 0; }
    for (int c = 0; c < 4 * KNN; ++c)
        topk_insert(s1d[(size_t)q * 64 + c], s1i[(size_t)q * 64 + c], d, id);
#pragma unroll
    for (int t = 0; t < KNN; ++t) outidx[q * KNN + t] = id[t];
}

// ----------------------------------------------------------------------------
// SGEMM: C[M,N] = A[M,K] @ B[K,N]   (row-major).
// A element (m,k) read at A[(m*arstride)*lda + k].
// MODE 0: store.  MODE 1: C += acc.  MODE 2: C = relu(acc*s + b) (per-column).
// ----------------------------------------------------------------------------
template <int MODE>
__global__ void sgemm_kernel(const float* __restrict__ A, int lda, int arstride,
                             const float* __restrict__ B, int ldb,
                             float* __restrict__ C, int ldc,
                             int M, int N, int Kd,
                             const float* __restrict__ scv, const float* __restrict__ biv) {
    const int BM = 64, BN = 64, BK = 16;
    __shared__ float As[BK][BM];
    __shared__ float Bs[BK][BN];
    int bm = blockIdx.y * BM, bn = blockIdx.x * BN;
    int tid = threadIdx.x;
    int tr = (tid >> 4) << 2;
    int tc = (tid & 15) << 2;
    float acc[4][4];
#pragma unroll
    for (int i = 0; i < 4; ++i)
#pragma unroll
        for (int j = 0; j < 4; ++j) acc[i][j] = 0.f;

    for (int k0 = 0; k0 < Kd; k0 += BK) {
#pragma unroll
        for (int l = 0; l < 4; ++l) {
            int i = tid + l * 256;
            int m = i >> 4, k = i & 15;
            int gm = bm + m, gk = k0 + k;
            As[k][m] = (gm < M && gk < Kd) ? A[(size_t)gm * arstride * lda + gk] : 0.f;
        }
#pragma unroll
        for (int l = 0; l < 4; ++l) {
            int i = tid + l * 256;
            int k = i >> 6, n = i & 63;
            int gk = k0 + k, gn = bn + n;
            Bs[k][n] = (gk < Kd && gn < N) ? B[(size_t)gk * ldb + gn] : 0.f;
        }
        __syncthreads();
#pragma unroll
        for (int k = 0; k < BK; ++k) {
            float ar[4], br[4];
#pragma unroll
            for (int j = 0; j < 4; ++j) { ar[j] = As[k][tr + j]; br[j] = Bs[k][tc + j]; }
#pragma unroll
            for (int i = 0; i < 4; ++i)
#pragma unroll
                for (int j = 0; j < 4; ++j) acc[i][j] = fmaf(ar[i], br[j], acc[i][j]);
        }
        __syncthreads();
    }

#pragma unroll
    for (int i = 0; i < 4; ++i) {
        int gm = bm + tr + i; if (gm >= M) continue;
#pragma unroll
        for (int j = 0; j < 4; ++j) {
            int gn = bn + tc + j; if (gn >= N) continue;
            size_t off = (size_t)gm * ldc + gn;
            float v = acc[i][j];
            if (MODE == 1) v += C[off];
            if (MODE == 2) v = fmaxf(fmaf(v, scv[gn], biv[gn]), 0.f);
            C[off] = v;
        }
    }
}

// ----------------------------------------------------------------------------
// edge_conv gather-max: out[i,c] = max_k relu((A[i,c] + B[idx[i,k],c])*s[c]+b[c])
// ----------------------------------------------------------------------------
__global__ void gathermax_kernel(const float* __restrict__ Aa, const float* __restrict__ Bb,
                                 const int* __restrict__ idx,
                                 const float* __restrict__ s, const float* __restrict__ b,
                                 float* __restrict__ out, int C) {
    int i = blockIdx.x, c = threadIdx.x;
    __shared__ int js[KNN];
    if (c < KNN) js[c] = idx[i * KNN + c];
    __syncthreads();
    float a = Aa[(size_t)i * C + c];
    float sc = s[c], bv = b[c];
    float m = 0.f;  // relu outputs are >= 0
#pragma unroll
    for (int k = 0; k < KNN; ++k) {
        float v = fmaf(a + Bb[(size_t)js[k] * C + c], sc, bv);
        m = fmaxf(m, v);
    }
    out[(size_t)i * C + c] = m;
}

// ----------------------------------------------------------------------------
// graph attention over 16 neighbors. block = D threads (one point per block).
// ----------------------------------------------------------------------------
template <int D>
__global__ void attn_kernel(const float* __restrict__ q, const float* __restrict__ kk,
                            const float* __restrict__ v, const int* __restrict__ idx,
                            const float* __restrict__ s, const float* __restrict__ b,
                            float* __restrict__ out) {
    int i = blockIdx.x;
    int tid = threadIdx.x;
    __shared__ float qs[D];
    __shared__ float lg[KNN];
    __shared__ float aw[KNN];
    __shared__ int js[KNN];
    qs[tid] = q[(size_t)i * D + tid];
    if (tid < KNN) js[tid] = idx[i * KNN + tid];
    __syncthreads();

    const int NW = D / 32;
    int w = tid >> 5, lane = tid & 31;
    for (int k = w; k < KNN; k += NW) {
        const float* kr = kk + (size_t)js[k] * D;
        float sum = 0.f;
#pragma unroll
        for (int m = lane; m < D; m += 32) sum = fmaf(qs[m], kr[m], sum);
#pragma unroll
        for (int o = 16; o; o >>= 1) sum += __shfl_xor_sync(0xffffffffu, sum, o);
        if (lane == 0) lg[k] = sum * (1.f / sqrtf((float)D));
    }
    __syncthreads();
    if (tid < 32) {
        float l = (lane < KNN) ? lg[lane] : -FLT_MAX;
        float mx = l;
#pragma unroll
        for (int o = 16; o; o >>= 1) mx = fmaxf(mx, __shfl_xor_sync(0xffffffffu, mx, o));
        float e = (lane < KNN) ? expf(l - mx) : 0.f;
        float se = e;
#pragma unroll
        for (int o = 16; o; o >>= 1) se += __shfl_xor_sync(0xffffffffu, se, o);
        if (lane < KNN) aw[lane] = e / se;
    }
    __syncthreads();
    float y = 0.f;
#pragma unroll
    for (int k = 0; k < KNN; ++k) y = fmaf(aw[k], v[(size_t)js[k] * D + tid], y);
    float r = fmaf(y, s[tid], b[tid]);
    out[(size_t)i * D + tid] = fmaxf(r, 0.f);
}

// ----------------------------------------------------------------------------
// downsample gather-max: xd[i,c] = max_k relu((PX[idxd[i,k],c]-Pm[i,c])*sd[c]+bd[c])
// ----------------------------------------------------------------------------
__global__ void downgather_kernel(const float* __restrict__ PX, const float* __restrict__ Pm,
                                  const int* __restrict__ idxd,
                                  const float* __restrict__ s, const float* __restrict__ b,
                                  float* __restrict__ out) {
    int i = blockIdx.x, c = threadIdx.x;  // block 512
    __shared__ int js[KNN];
    if (c < KNN) js[c] = idxd[i * KNN + c];
    __syncthreads();
    float pm = Pm[(size_t)i * 512 + c];
    float sc = s[c], bv = b[c];
    float m = 0.f;
#pragma unroll
    for (int k = 0; k < KNN; ++k) {
        float v = fmaf(PX[(size_t)js[k] * 512 + c] - pm, sc, bv);
        m = fmaxf(m, v);
    }
    out[(size_t)i * 512 + c] = m;
}

// column sums of xd [2048,512] -> gsum[512]  (deterministic, grid 4 x 128)
__global__ void colsum_kernel(const float* __restrict__ xd, float* __restrict__ gsum) {
    int c = blockIdx.x * blockDim.x + threadIdx.x;
    if (c >= 512) return;
    float s = 0.f;
    for (int r = 0; r < NDOWN; ++r) s += xd[(size_t)r * 512 + c];
    gsum[c] = s;
}

// beff[c] = bu1[c] + bu2[c] + su2[c] * ((gsum/2048) @ Wu2)[c]   (1 block, 256 thr)
__global__ void beff_kernel(const float* __restrict__ gsum, const float* __restrict__ Wu2,
                            const float* __restrict__ su2, const float* __restrict__ bu1,
                            const float* __restrict__ bu2, float* __restrict__ be) {
    int c = threadIdx.x;
    float acc = 0.f;
    for (int d = 0; d < 512; ++d) acc = fmaf(gsum[d], Wu2[(size_t)d * 256 + c], acc);
    be[c] = bu1[c] + bu2[c] + su2[c] * (acc * (1.f / 2048.f));
}

// b2eff[c] = bc1[c]*sc[c] + bc[c]   (1 block, 128 thr)
__global__ void b2eff_kernel(const float* __restrict__ bc1, const float* __restrict__ scv,
                             const float* __restrict__ bcv, float* __restrict__ o) {
    int c = threadIdx.x;
    o[c] = fmaf(bc1[c], scv[c], bcv[c]);
}

// Wd[t] = W[t] - W[half + t]
__global__ void wdiff_kernel(const float* __restrict__ W, int half, float* __restrict__ Wd) {
    int t = blockIdx.x * blockDim.x + threadIdx.x;
    if (t < half) Wd[t] = W[t] - W[half + t];
}

// out[i,c] = h[i,:] @ Wc2[:,c] + bc2[c]   (2048 x 6)
__global__ void final_kernel(const float* __restrict__ h, const float* __restrict__ Wc2,
                             const float* __restrict__ bc2, float* __restrict__ out) {
    int t = blockIdx.x * blockDim.x + threadIdx.x;
    if (t >= NDOWN * 6) return;
    int i = t / 6, c = t % 6;
    float acc = bc2[c];
    for (int d = 0; d < 128; ++d) acc = fmaf(h[(size_t)i * 128 + d], Wc2[d * 6 + c], acc);
    out[t] = acc;
}

// ----------------------------------------------------------------------------
// launch
// ----------------------------------------------------------------------------
static void sgemm(int mode, const float* A, int lda, int ars, const float* B, int ldb,
                  float* C, int M, int N, int K, const float* s = nullptr, const float* b = nullptr) {
    dim3 g((N + 63) / 64, (M + 63) / 64);
    if (mode == 0)      sgemm_kernel<0><<<g, 256>>>(A, lda, ars, B, ldb, C, N, M, N, K, s, b);
    else if (mode == 1) sgemm_kernel<1><<<g, 256>>>(A, lda, ars, B, ldb, C, N, M, N, K, s, b);
    else                sgemm_kernel<2><<<g, 256>>>(A, lda, ars, B, ldb, C, N, M, N, K, s, b);
}

extern "C" void kernel_launch(void* const* d_in, const int* in_sizes, int n_in,
                              void* d_out, int out_size) {
    const float* points = (const float*)d_in[0];
    const float* We1 = (const float*)d_in[1];
    const float* se1 = (const float*)d_in[2];
    const float* be1 = (const float*)d_in[3];
    const float* We2 = (const float*)d_in[4];
    const float* se2 = (const float*)d_in[5];
    const float* be2 = (const float*)d_in[6];
    const float* Wq1 = (const float*)d_in[7];
    const float* Wk1 = (const float*)d_in[8];
    const float* Wv1 = (const float*)d_in[9];
    const float* sa1 = (const float*)d_in[10];
    const float* ba1 = (const float*)d_in[11];
    const float* Wq2 = (const float*)d_in[12];
    const float* Wk2 = (const float*)d_in[13];
    const float* Wv2 = (const float*)d_in[14];
    const float* sa2 = (const float*)d_in[15];
    const float* ba2 = (const float*)d_in[16];
    const float* Wtd = (const float*)d_in[17];
    const float* sd  = (const float*)d_in[18];
    const float* bd  = (const float*)d_in[19];
    const float* Wu1 = (const float*)d_in[20];
    const float* su1 = (const float*)d_in[21];
    const float* bu1 = (const float*)d_in[22];
    const float* Wu2 = (const float*)d_in[23];
    const float* su2 = (const float*)d_in[24];
    const float* bu2 = (const float*)d_in[25];
    const float* Wc1 = (const float*)d_in[26];
    const float* bc1 = (const float*)d_in[27];
    const float* scv = (const float*)d_in[28];
    const float* bcv = (const float*)d_in[29];
    const float* Wc2 = (const float*)d_in[30];
    const float* bc2 = (const float*)d_in[31];

    float* F = nullptr;
    int*   I = nullptr;
    cudaGetSymbolAddress((void**)&F, g_f);
    cudaGetSymbolAddress((void**)&I, g_i);

    float4* p4  = (float4*)(F + O_P4);
    float*  s1d = F + O_S1D;
    int*    s1i = I + OI_S1I;
    int*    idx = I + OI_IDX;
    int*    idxd = I + OI_IDXD;

    // --- kNN (full + downsampled) ---
    prep_p4_kernel<<<(NPTS + 127) / 128, 128>>>(points, p4);
    {
        dim3 g1(NPTS / 128, 4);
        knn_stage1_kernel<<<g1, 128>>>(p4, 1, s1d, s1i);
        knn_stage2_kernel<<<NPTS / 128, 128>>>(s1d, s1i, NPTS, idx);
        dim3 g2(NDOWN / 128, 4);
        knn_stage1_kernel<<<g2, 128>>>(p4, 4, s1d, s1i);
        knn_stage2_kernel<<<NDOWN / 128, 128>>>(s1d, s1i, NDOWN, idxd);
    }

    // --- edge_conv 1: x1 = max_k relu((p@(Wt-Wb) + p_j@Wb)*s+b), C=64 ---
    wdiff_kernel<<<(192 + 127) / 128, 128>>>(We1, 192, F + O_WD1);
    sgemm(0, points, 3, 1, F + O_WD1, 64, F + O_A1, NPTS, 64, 3);
    sgemm(0, points, 3, 1, We1 + 192, 64, F + O_B1, NPTS, 64, 3);
    gathermax_kernel<<<NPTS, 64>>>(F + O_A1, F + O_B1, idx, se1, be1, F + O_X1, 64);

    // --- edge_conv 2: C=128 ---
    wdiff_kernel<<<(8192 + 127) / 128, 128>>>(We2, 8192, F + O_WD2);
    sgemm(0, F + O_X1, 64, 1, F + O_WD2, 128, F + O_A2, NPTS, 128, 64);
    sgemm(0, F + O_X1, 64, 1, We2 + 8192, 128, F + O_B2, NPTS, 128, 64);
    gathermax_kernel<<<NPTS, 128>>>(F + O_A2, F + O_B2, idx, se2, be2, F + O_X2, 128);

    // --- graph_attn 1: D=256 ---
    sgemm(0, F + O_X2, 128, 1, Wq1, 256, F + O_Q1, NPTS, 256, 128);
    sgemm(0, F + O_X2, 128, 1, Wk1, 256, F + O_K1, NPTS, 256, 128);
    sgemm(0, F + O_X2, 128, 1, Wv1, 256, F + O_V1, NPTS, 256, 128);
    attn_kernel<256><<<NPTS, 256>>>(F + O_Q1, F + O_K1, F + O_V1, idx, sa1, ba1, F + O_X3);

    // --- graph_attn 2: D=512 ---
    sgemm(0, F + O_X3, 256, 1, Wq2, 512, F + O_Q2, NPTS, 512, 256);
    sgemm(0, F + O_X3, 256, 1, Wk2, 512, F + O_K2, NPTS, 512, 256);
    sgemm(0, F + O_X3, 256, 1, Wv2, 512, F + O_V2, NPTS, 512, 256);
    attn_kernel<512><<<NPTS, 512>>>(F + O_Q2, F + O_K2, F + O_V2, idx, sa2, ba2, F + O_X4);

    // --- downsample layer: PX = p@Wtd[0:3] + x4@Wtd[3:], Pm = pm@Wtd[0:3] ---
    sgemm(0, points, 3, 1, Wtd, 512, F + O_PX, NPTS, 512, 3);
    sgemm(1, F + O_X4, 512, 1, Wtd + 3 * 512, 512, F + O_PX, NPTS, 512, 512);
    sgemm(0, points, 3, 4, Wtd, 512, F + O_PM, NDOWN, 512, 3);
    downgather_kernel<<<NDOWN, 512>>>(F + O_PX, F + O_PM, idxd, sd, bd, F + O_XD);

    // --- global mean branch folded into bias, then xu = relu(xd@Wu1*su1 + beff) ---
    colsum_kernel<<<4, 128>>>(F + O_XD, F + O_GS);
    beff_kernel<<<1, 256>>>(F + O_GS, Wu2, su2, bu1, bu2, F + O_BE);
    sgemm(2, F + O_XD, 512, 1, Wu1, 256, F + O_XU, NDOWN, 256, 512, su1, F + O_BE);

    // --- h = relu((xu@Wc1 + bc1)*sc + bc) = relu(acc*sc + (bc1*sc+bc)) ---
    b2eff_kernel<<<1, 128>>>(bc1, scv, bcv, F + O_B2E);
    sgemm(2, F + O_XU, 256, 1, Wc1, 128, F + O_H, NDOWN, 128, 256, scv, F + O_B2E);

    // --- out = h@Wc2 + bc2 ---
    final_kernel<<<(NDOWN * 6 + 127) / 128, 128>>>(F + O_H, Wc2, bc2, (float*)d_out);
}

// round 2
// speedup vs baseline: 1.1890x; 1.1890x over previous
#include <cuda_runtime.h>
#include <math.h>
#include <float.h>

#define NPTS   8192
#define NDOWN  2048
#define KNN    16
#define CHUNKS 8

// ----------------------------------------------------------------------------
// Scratch arenas (no cudaMalloc allowed).
// ----------------------------------------------------------------------------
__device__ float g_f[38200000];
__device__ int   g_i[1250000];

// float offsets
static const size_t O_A1  = 0;                          // 8192*64 (unused now, kept slot)
static const size_t O_B1  = O_A1  + (size_t)8192*64;
static const size_t O_X1  = O_B1  + (size_t)8192*64;
static const size_t O_A2  = O_X1  + (size_t)8192*64;    // 8192*128
static const size_t O_B2  = O_A2  + (size_t)8192*128;
static const size_t O_X2  = O_B2  + (size_t)8192*128;
static const size_t O_Q1  = O_X2  + (size_t)8192*128;   // 8192*256
static const size_t O_K1  = O_Q1  + (size_t)8192*256;
static const size_t O_V1  = O_K1  + (size_t)8192*256;
static const size_t O_X3  = O_V1  + (size_t)8192*256;
static const size_t O_Q2  = O_X3  + (size_t)8192*256;   // 8192*512
static const size_t O_K2  = O_Q2  + (size_t)8192*512;
static const size_t O_V2  = O_K2  + (size_t)8192*512;
static const size_t O_X4  = O_V2  + (size_t)8192*512;
static const size_t O_PX  = O_X4  + (size_t)8192*512;
static const size_t O_PM  = O_PX  + (size_t)8192*512;   // 2048*512
static const size_t O_XD  = O_PM  + (size_t)2048*512;
static const size_t O_XU  = O_XD  + (size_t)2048*512;   // 2048*256
static const size_t O_H   = O_XU  + (size_t)2048*256;   // 2048*128
static const size_t O_GS  = O_H   + (size_t)2048*128;   // 512
static const size_t O_BE  = O_GS  + 512;                // 256
static const size_t O_B2E = O_BE  + 256;                // 128
static const size_t O_WD1 = O_B2E + 128;                // 3*64
static const size_t O_WD2 = O_WD1 + 192;                // 64*128
static const size_t O_P4  = O_WD2 + 8192;               // 8192*4 (float4-aligned)
static const size_t O_S1D = O_P4  + (size_t)8192*4;     // 8192*128

// int offsets
static const size_t OI_IDX  = 0;                         // 8192*16
static const size_t OI_IDXD = (size_t)8192*16;           // 2048*16
static const size_t OI_S1I  = OI_IDXD + (size_t)2048*16; // 8192*128

// ----------------------------------------------------------------------------
// f32x2 helpers (Blackwell packed fp32)
// ----------------------------------------------------------------------------
typedef unsigned long long ull;

__device__ __forceinline__ ull pk2(float lo, float hi) {
    ull r; asm("mov.b64 %0,{%1,%2};" : "=l"(r) : "f"(lo), "f"(hi)); return r;
}
__device__ __forceinline__ ull fma2(ull a, ull b, ull c) {
    ull d; asm("fma.rn.f32x2 %0,%1,%2,%3;" : "=l"(d) : "l"(a), "l"(b), "l"(c)); return d;
}
__device__ __forceinline__ void upk2(ull v, float& lo, float& hi) {
    asm("mov.b64 {%0,%1},%2;" : "=f"(lo), "=f"(hi) : "l"(v));
}

// ----------------------------------------------------------------------------
// kNN: unordered top-16 with lazy threshold + 4-deep accept buffer.
// ----------------------------------------------------------------------------
__device__ __forceinline__ void replace_rescan(float s, int j, float (&d)[KNN], int (&id)[KNN],
                                               float& wval, int& wpos) {
#pragma unroll
    for (int t = 0; t < KNN; ++t) if (t == wpos) { d[t] = s; id[t] = j; }
    wval = d[0]; wpos = 0;
#pragma unroll
    for (int t = 1; t < KNN; ++t) if (d[t] > wval) { wval = d[t]; wpos = t; }
}

__global__ void prep_p4_kernel(const float* __restrict__ p, float4* __restrict__ p4) {
    int i = blockIdx.x * blockDim.x + threadIdx.x;
    if (i < NPTS) {
        float x = p[3 * i], y = p[3 * i + 1], z = p[3 * i + 2];
        p4[i] = make_float4(x, y, z, x * x + y * y + z * z);
    }
}

// grid (nq/128, CHUNKS), block 128. score = |pj|^2 - 2 q.pj (same ranking as d2)
__global__ void knn_stage1_kernel(const float4* __restrict__ p4, int qstride,
                                  float* __restrict__ s1d, int* __restrict__ s1i) {
    const int CH = NPTS / CHUNKS;  // 1024
    int q  = blockIdx.x * blockDim.x + threadIdx.x;
    int c0 = blockIdx.y * CH;

    float4 qp = p4[q * qstride];
    float qx = -2.f * qp.x, qy = -2.f * qp.y, qz = -2.f * qp.z;

    float d[KNN]; int id[KNN];
    float wval; int wpos;
    float bs0, bs1, bs2, bs3; int bj0, bj1, bj2, bj3; int cnt = 0;
    bs0 = bs1 = bs2 = bs3 = 0.f; bj0 = bj1 = bj2 = bj3 = 0;

    __shared__ float4 tile[512];

    for (int t0 = 0; t0 < CH; t0 += 512) {
        __syncthreads();
#pragma unroll
        for (int l = 0; l < 4; ++l) tile[threadIdx.x + l * 128] = p4[c0 + t0 + threadIdx.x + l * 128];
        __syncthreads();
        int istart = 0;
        if (t0 == 0) {
#pragma unroll
            for (int t = 0; t < KNN; ++t) {
                float4 c = tile[t];
                d[t] = fmaf(qx, c.x, fmaf(qy, c.y, fmaf(qz, c.z, c.w)));
                id[t] = c0 + t;
            }
            wval = d[0]; wpos = 0;
#pragma unroll
            for (int t = 1; t < KNN; ++t) if (d[t] > wval) { wval = d[t]; wpos = t; }
            istart = KNN;
        }
        for (int i = istart; i < 512; ++i) {
            float4 c = tile[i];
            float s = fmaf(qx, c.x, fmaf(qy, c.y, fmaf(qz, c.z, c.w)));
            if (s < wval) {
                int j = c0 + t0 + i;
                if (cnt == 0)      { bs0 = s; bj0 = j; }
                else if (cnt == 1) { bs1 = s; bj1 = j; }
                else if (cnt == 2) { bs2 = s; bj2 = j; }
                else               { bs3 = s; bj3 = j; }
                cnt++;
            }
            if (__any_sync(0xffffffffu, cnt == 4)) {
                if (cnt > 0 && bs0 < wval) replace_rescan(bs0, bj0, d, id, wval, wpos);
                if (cnt > 1 && bs1 < wval) replace_rescan(bs1, bj1, d, id, wval, wpos);
                if (cnt > 2 && bs2 < wval) replace_rescan(bs2, bj2, d, id, wval, wpos);
                if (cnt > 3 && bs3 < wval) replace_rescan(bs3, bj3, d, id, wval, wpos);
                cnt = 0;
            }
        }
    }
    // final flush
    if (cnt > 0 && bs0 < wval) replace_rescan(bs0, bj0, d, id, wval, wpos);
    if (cnt > 1 && bs1 < wval) replace_rescan(bs1, bj1, d, id, wval, wpos);
    if (cnt > 2 && bs2 < wval) replace_rescan(bs2, bj2, d, id, wval, wpos);
    if (cnt > 3 && bs3 < wval) replace_rescan(bs3, bj3, d, id, wval, wpos);

    size_t o = ((size_t)q * CHUNKS + blockIdx.y) * KNN;
#pragma unroll
    for (int t = 0; t < KNN; ++t) { s1d[o + t] = d[t]; s1i[o + t] = id[t]; }
}

__global__ void knn_stage2_kernel(const float* __restrict__ s1d, const int* __restrict__ s1i,
                                  int nq, int* __restrict__ outidx) {
    int q = blockIdx.x * blockDim.x + threadIdx.x;
    if (q >= nq) return;
    size_t base = (size_t)q * (CHUNKS * KNN);
    float d[KNN]; int id[KNN];
#pragma unroll
    for (int t = 0; t < KNN; ++t) { d[t] = s1d[base + t]; id[t] = s1i[base + t]; }
    float wval = d[0]; int wpos = 0;
#pragma unroll
    for (int t = 1; t < KNN; ++t) if (d[t] > wval) { wval = d[t]; wpos = t; }
    for (int c = KNN; c < CHUNKS * KNN; ++c) {
        float s = s1d[base + c];
        if (s < wval) replace_rescan(s, s1i[base + c], d, id, wval, wpos);
    }
#pragma unroll
    for (int t = 0; t < KNN; ++t) outidx[q * KNN + t] = id[t];
}

// ----------------------------------------------------------------------------
// GEMM: C[M,N] = A[M,K] @ B[K,N], row-major, f32x2 packed FMA.
// Requires M % BM == 0, N % BN == 0, K % 16 == 0, all pointers 16B aligned.
// MODE 0: store.  MODE 1: C += acc.  MODE 2: C = relu(acc*s + b) per-column.
// block = 256 threads; microtile (BM/16) x (BN/16).
// ----------------------------------------------------------------------------
template <int BM, int BN, int MODE>
__global__ __launch_bounds__(256)
void gemm_kernel(const float* __restrict__ A, int lda,
                 const float* __restrict__ B, int ldb,
                 float* __restrict__ C, int ldc, int K,
                 const float* __restrict__ scv, const float* __restrict__ biv) {
    constexpr int TM = BM / 16;      // rows per thread (8 or 4)
    constexpr int TN = BN / 16;      // cols per thread (8 or 4)
    constexpr int RP = TM / 2;       // row pairs
    constexpr int NA = BM / 64;      // float4 A loads per thread
    constexpr int NB = BN / 64;      // float4 B loads per thread
    constexpr int F4R = BN / 4;      // float4s per B row
    constexpr int BROW = 256 / F4R;  // B rows loaded per 256-thread batch

    __shared__ __align__(16) float As[16][BM + 4];
    __shared__ __align__(16) float Bs[16][BN];

    int tid = threadIdx.x;
    int bm = blockIdx.y * BM, bn = blockIdx.x * BN;

    int ar = tid >> 2, ac4 = tid & 3;          // A loader: row, col-group
    int bk = tid / F4R, bc = tid % F4R;        // B loader: k-row, col-group

    const float* Ap = A + (size_t)(bm + ar) * lda + ac4 * 4;
    const float* Bp = B + (size_t)bk * ldb + bn + bc * 4;

    float4 pa[NA], pb[NB];
#pragma unroll
    for (int l = 0; l < NA; ++l) pa[l] = *(const float4*)(Ap + (size_t)(64 * l) * lda);
#pragma unroll
    for (int l = 0; l < NB; ++l) pb[l] = *(const float4*)(Bp + (size_t)(BROW * l) * ldb);
    Ap += 16;
    Bp += (size_t)16 * ldb;

    int tr = (tid >> 4) * TM;
    int tc = (tid & 15) * TN;

    ull acc[RP][TN];
#pragma unroll
    for (int rp = 0; rp < RP; ++rp)
#pragma unroll
        for (int c = 0; c < TN; ++c) acc[rp][c] = 0ull;

    int ktiles = K >> 4;
    for (int t = 0; t < ktiles; ++t) {
        // store staged tile
#pragma unroll
        for (int l = 0; l < NA; ++l) {
            int r = ar + 64 * l;
            As[ac4 * 4 + 0][r] = pa[l].x;
            As[ac4 * 4 + 1][r] = pa[l].y;
            As[ac4 * 4 + 2][r] = pa[l].z;
            As[ac4 * 4 + 3][r] = pa[l].w;
        }
#pragma unroll
        for (int l = 0; l < NB; ++l)
            *(float4*)&Bs[bk + BROW * l][bc * 4] = pb[l];
        __syncthreads();

        if (t + 1 < ktiles) {
#pragma unroll
            for (int l = 0; l < NA; ++l) pa[l] = *(const float4*)(Ap + (size_t)(64 * l) * lda);
#pragma unroll
            for (int l = 0; l < NB; ++l) pb[l] = *(const float4*)(Bp + (size_t)(BROW * l) * ldb);
            Ap += 16;
            Bp += (size_t)16 * ldb;
        }

#pragma unroll
        for (int k = 0; k < 16; ++k) {
            float4 av[TM / 4], bv[TN / 4];
#pragma unroll
            for (int v = 0; v < TM / 4; ++v) av[v] = *(const float4*)&As[k][tr + 4 * v];
#pragma unroll
            for (int v = 0; v < TN / 4; ++v) bv[v] = *(const float4*)&Bs[k][tc + 4 * v];
            ull apk[RP];
#pragma unroll
            for (int v = 0; v < TM / 4; ++v) {
                apk[2 * v + 0] = pk2(av[v].x, av[v].y);
                apk[2 * v + 1] = pk2(av[v].z, av[v].w);
            }
#pragma unroll
            for (int v = 0; v < TN / 4; ++v) {
                {
                    ull bb = pk2(bv[v].x, bv[v].x);
#pragma unroll
                    for (int rp = 0; rp < RP; ++rp) acc[rp][4 * v + 0] = fma2(apk[rp], bb, acc[rp][4 * v + 0]);
                }
                {
                    ull bb = pk2(bv[v].y, bv[v].y);
#pragma unroll
                    for (int rp = 0; rp < RP; ++rp) acc[rp][4 * v + 1] = fma2(apk[rp], bb, acc[rp][4 * v + 1]);
                }
                {
                    ull bb = pk2(bv[v].z, bv[v].z);
#pragma unroll
                    for (int rp = 0; rp < RP; ++rp) acc[rp][4 * v + 2] = fma2(apk[rp], bb, acc[rp][4 * v + 2]);
                }
                {
                    ull bb = pk2(bv[v].w, bv[v].w);
#pragma unroll
                    for (int rp = 0; rp < RP; ++rp) acc[rp][4 * v + 3] = fma2(apk[rp], bb, acc[rp][4 * v + 3]);
                }
            }
        }
        __syncthreads();
    }

    // epilogue
    float sc8[TN], bi8[TN];
    if (MODE == 2) {
#pragma unroll
        for (int c = 0; c < TN; ++c) { sc8[c] = scv[bn + tc + c]; bi8[c] = biv[bn + tc + c]; }
    }
#pragma unroll
    for (int rp = 0; rp < RP; ++rp) {
        int r0 = bm + tr + 2 * rp, r1 = r0 + 1;
        float o0[TN], o1[TN];
#pragma unroll
        for (int c = 0; c < TN; ++c) upk2(acc[rp][c], o0[c], o1[c]);
        if (MODE == 1) {
#pragma unroll
            for (int v = 0; v < TN / 4; ++v) {
                float4 c0 = *(const float4*)&C[(size_t)r0 * ldc + bn + tc + 4 * v];
                float4 c1 = *(const float4*)&C[(size_t)r1 * ldc + bn + tc + 4 * v];
                o0[4 * v + 0] += c0.x; o0[4 * v + 1] += c0.y; o0[4 * v + 2] += c0.z; o0[4 * v + 3] += c0.w;
                o1[4 * v + 0] += c1.x; o1[4 * v + 1] += c1.y; o1[4 * v + 2] += c1.z; o1[4 * v + 3] += c1.w;
            }
        }
        if (MODE == 2) {
#pragma unroll
            for (int c = 0; c < TN; ++c) {
                o0[c] = fmaxf(fmaf(o0[c], sc8[c], bi8[c]), 0.f);
                o1[c] = fmaxf(fmaf(o1[c], sc8[c], bi8[c]), 0.f);
            }
        }
#pragma unroll
        for (int v = 0; v < TN / 4; ++v) {
            *(float4*)&C[(size_t)r0 * ldc + bn + tc + 4 * v] =
                make_float4(o0[4 * v], o0[4 * v + 1], o0[4 * v + 2], o0[4 * v + 3]);
            *(float4*)&C[(size_t)r1 * ldc + bn + tc + 4 * v] =
                make_float4(o1[4 * v], o1[4 * v + 1], o1[4 * v + 2], o1[4 * v + 3]);
        }
    }
}

// ----------------------------------------------------------------------------
// edge_conv1 fully fused (K=3): x1[i,c] = max_k relu((p_i@Wd + p_j@Wb)[c]*s+b)
// ----------------------------------------------------------------------------
__global__ void edge1_kernel(const float4* __restrict__ p4,
                             const float* __restrict__ Wd, const float* __restrict__ Wb,
                             const int* __restrict__ idx,
                             const float* __restrict__ s, const float* __restrict__ b,
                             float* __restrict__ out) {
    __shared__ float4 pj[KNN];
    int i = blockIdx.x, c = threadIdx.x;  // block 64
    if (c < KNN) pj[c] = p4[idx[i * KNN + c]];
    __syncthreads();
    float4 pi = p4[i];
    float w0 = Wd[c], w1 = Wd[64 + c], w2 = Wd[128 + c];
    float u0 = Wb[c], u1 = Wb[64 + c], u2 = Wb[128 + c];
    float a = fmaf(pi.x, w0, fmaf(pi.y, w1, pi.z * w2));
    float sc = s[c], bv = b[c];
    float m = 0.f;
#pragma unroll
    for (int k = 0; k < KNN; ++k) {
        float4 pp = pj[k];
        float e = fmaf(pp.x, u0, fmaf(pp.y, u1, fmaf(pp.z, u2, a)));
        m = fmaxf(m, fmaf(e, sc, bv));
    }
    out[(size_t)i * 64 + c] = m;
}

// ----------------------------------------------------------------------------
// edge_conv2 gather-max: out[i,c] = max_k relu((A[i,c]+B[idx[i,k],c])*s[c]+b[c])
// ----------------------------------------------------------------------------
__global__ void gathermax_kernel(const float* __restrict__ Aa, const float* __restrict__ Bb,
                                 const int* __restrict__ idx,
                                 const float* __restrict__ s, const float* __restrict__ b,
                                 float* __restrict__ out, int C) {
    int i = blockIdx.x, c = threadIdx.x;
    __shared__ int js[KNN];
    if (c < KNN) js[c] = idx[i * KNN + c];
    __syncthreads();
    float a = Aa[(size_t)i * C + c];
    float sc = s[c], bv = b[c];
    float m = 0.f;
#pragma unroll
    for (int k = 0; k < KNN; ++k) {
        float v = fmaf(a + Bb[(size_t)js[k] * C + c], sc, bv);
        m = fmaxf(m, v);
    }
    out[(size_t)i * C + c] = m;
}

// ----------------------------------------------------------------------------
// graph attention over 16 neighbors; block = D threads.
// ----------------------------------------------------------------------------
template <int D>
__global__ void attn_kernel(const float* __restrict__ q, const float* __restrict__ kk,
                            const float* __restrict__ v, const int* __restrict__ idx,
                            const float* __restrict__ s, const float* __restrict__ b,
                            float* __restrict__ out) {
    int i = blockIdx.x;
    int tid = threadIdx.x;
    __shared__ float qs[D];
    __shared__ float lg[KNN];
    __shared__ float aw[KNN];
    __shared__ int js[KNN];
    qs[tid] = q[(size_t)i * D + tid];
    if (tid < KNN) js[tid] = idx[i * KNN + tid];
    __syncthreads();

    const int NW = D / 32;
    int w = tid >> 5, lane = tid & 31;
    for (int k = w; k < KNN; k += NW) {
        const float* kr = kk + (size_t)js[k] * D;
        float sum = 0.f;
#pragma unroll
        for (int m = lane; m < D; m += 32) sum = fmaf(qs[m], kr[m], sum);
#pragma unroll
        for (int o = 16; o; o >>= 1) sum += __shfl_xor_sync(0xffffffffu, sum, o);
        if (lane == 0) lg[k] = sum * (1.f / sqrtf((float)D));
    }
    __syncthreads();
    if (tid < 32) {
        float l = (lane < KNN) ? lg[lane] : -FLT_MAX;
        float mx = l;
#pragma unroll
        for (int o = 16; o; o >>= 1) mx = fmaxf(mx, __shfl_xor_sync(0xffffffffu, mx, o));
        float e = (lane < KNN) ? expf(l - mx) : 0.f;
        float se = e;
#pragma unroll
        for (int o = 16; o; o >>= 1) se += __shfl_xor_sync(0xffffffffu, se, o);
        if (lane < KNN) aw[lane] = e / se;
    }
    __syncthreads();
    float y = 0.f;
#pragma unroll
    for (int k = 0; k < KNN; ++k) y = fmaf(aw[k], v[(size_t)js[k] * D + tid], y);
    float r = fmaf(y, s[tid], b[tid]);
    out[(size_t)i * D + tid] = fmaxf(r, 0.f);
}

// ----------------------------------------------------------------------------
// K=3 row transform: out[i,c] = p.x*W[0,c] + p.y*W[1,c] + p.z*W[2,c]
// grid (rows, ncols/128), block 128; row i uses p4[i*rstride].
// ----------------------------------------------------------------------------
__global__ void rows3_kernel(const float4* __restrict__ p4, int rstride,
                             const float* __restrict__ W, float* __restrict__ out, int ncols) {
    int i = blockIdx.x;
    int c = blockIdx.y * blockDim.x + threadIdx.x;
    float4 p = p4[(size_t)i * rstride];
    out[(size_t)i * ncols + c] = fmaf(p.x, W[c], fmaf(p.y, W[ncols + c], p.z * W[2 * ncols + c]));
}

// ----------------------------------------------------------------------------
// downsample gather-max
// ----------------------------------------------------------------------------
__global__ void downgather_kernel(const float* __restrict__ PX, const float* __restrict__ Pm,
                                  const int* __restrict__ idxd,
                                  const float* __restrict__ s, const float* __restrict__ b,
                                  float* __restrict__ out) {
    int i = blockIdx.x, c = threadIdx.x;  // block 512
    __shared__ int js[KNN];
    if (c < KNN) js[c] = idxd[i * KNN + c];
    __syncthreads();
    float pm = Pm[(size_t)i * 512 + c];
    float sc = s[c], bv = b[c];
    float m = 0.f;
#pragma unroll
    for (int k = 0; k < KNN; ++k) {
        float v = fmaf(PX[(size_t)js[k] * 512 + c] - pm, sc, bv);
        m = fmaxf(m, v);
    }
    out[(size_t)i * 512 + c] = m;
}

__global__ void colsum_kernel(const float* __restrict__ xd, float* __restrict__ gsum) {
    int c = blockIdx.x * blockDim.x + threadIdx.x;
    if (c >= 512) return;
    float s = 0.f;
    for (int r = 0; r < NDOWN; ++r) s += xd[(size_t)r * 512 + c];
    gsum[c] = s;
}

__global__ void beff_kernel(const float* __restrict__ gsum, const float* __restrict__ Wu2,
                            const float* __restrict__ su2, const float* __restrict__ bu1,
                            const float* __restrict__ bu2, float* __restrict__ be) {
    int c = threadIdx.x;
    float acc = 0.f;
    for (int d = 0; d < 512; ++d) acc = fmaf(gsum[d], Wu2[(size_t)d * 256 + c], acc);
    be[c] = bu1[c] + bu2[c] + su2[c] * (acc * (1.f / 2048.f));
}

__global__ void b2eff_kernel(const float* __restrict__ bc1, const float* __restrict__ scv,
                             const float* __restrict__ bcv, float* __restrict__ o) {
    int c = threadIdx.x;
    o[c] = fmaf(bc1[c], scv[c], bcv[c]);
}

__global__ void wdiff_kernel(const float* __restrict__ W, int half, float* __restrict__ Wd) {
    int t = blockIdx.x * blockDim.x + threadIdx.x;
    if (t < half) Wd[t] = W[t] - W[half + t];
}

__global__ void final_kernel(const float* __restrict__ h, const float* __restrict__ Wc2,
                             const float* __restrict__ bc2, float* __restrict__ out) {
    int t = blockIdx.x * blockDim.x + threadIdx.x;
    if (t >= NDOWN * 6) return;
    int i = t / 6, c = t % 6;
    float acc = bc2[c];
    for (int d = 0; d < 128; ++d) acc = fmaf(h[(size_t)i * 128 + d], Wc2[d * 6 + c], acc);
    out[t] = acc;
}

// ----------------------------------------------------------------------------
// launch
// ----------------------------------------------------------------------------
extern "C" void kernel_launch(void* const* d_in, const int* in_sizes, int n_in,
                              void* d_out, int out_size) {
    const float* points = (const float*)d_in[0];
    const float* We1 = (const float*)d_in[1];
    const float* se1 = (const float*)d_in[2];
    const float* be1 = (const float*)d_in[3];
    const float* We2 = (const float*)d_in[4];
    const float* se2 = (const float*)d_in[5];
    const float* be2 = (const float*)d_in[6];
    const float* Wq1 = (const float*)d_in[7];
    const float* Wk1 = (const float*)d_in[8];
    const float* Wv1 = (const float*)d_in[9];
    const float* sa1 = (const float*)d_in[10];
    const float* ba1 = (const float*)d_in[11];
    const float* Wq2 = (const float*)d_in[12];
    const float* Wk2 = (const float*)d_in[13];
    const float* Wv2 = (const float*)d_in[14];
    const float* sa2 = (const float*)d_in[15];
    const float* ba2 = (const float*)d_in[16];
    const float* Wtd = (const float*)d_in[17];
    const float* sd  = (const float*)d_in[18];
    const float* bd  = (const float*)d_in[19];
    const float* Wu1 = (const float*)d_in[20];
    const float* su1 = (const float*)d_in[21];
    const float* bu1 = (const float*)d_in[22];
    const float* Wu2 = (const float*)d_in[23];
    const float* su2 = (const float*)d_in[24];
    const float* bu2 = (const float*)d_in[25];
    const float* Wc1 = (const float*)d_in[26];
    const float* bc1 = (const float*)d_in[27];
    const float* scv = (const float*)d_in[28];
    const float* bcv = (const float*)d_in[29];
    const float* Wc2 = (const float*)d_in[30];
    const float* bc2 = (const float*)d_in[31];

    float* F = nullptr;
    int*   I = nullptr;
    cudaGetSymbolAddress((void**)&F, g_f);
    cudaGetSymbolAddress((void**)&I, g_i);

    float4* p4  = (float4*)(F + O_P4);
    float*  s1d = F + O_S1D;
    int*    s1i = I + OI_S1I;
    int*    idx = I + OI_IDX;
    int*    idxd = I + OI_IDXD;

    // --- kNN (full + downsampled) ---
    prep_p4_kernel<<<(NPTS + 127) / 128, 128>>>(points, p4);
    {
        dim3 g1(NPTS / 128, CHUNKS);
        knn_stage1_kernel<<<g1, 128>>>(p4, 1, s1d, s1i);
        knn_stage2_kernel<<<NPTS / 128, 128>>>(s1d, s1i, NPTS, idx);
        dim3 g2(NDOWN / 128, CHUNKS);
        knn_stage1_kernel<<<g2, 128>>>(p4, 4, s1d, s1i);
        knn_stage2_kernel<<<NDOWN / 128, 128>>>(s1d, s1i, NDOWN, idxd);
    }

    // --- edge_conv 1 (fused, K=3, C=64) ---
    wdiff_kernel<<<2, 128>>>(We1, 192, F + O_WD1);
    edge1_kernel<<<NPTS, 64>>>(p4, F + O_WD1, We1 + 192, idx, se1, be1, F + O_X1);

    // --- edge_conv 2: C=128 ---
    wdiff_kernel<<<64, 128>>>(We2, 8192, F + O_WD2);
    gemm_kernel<128, 128, 0><<<dim3(1, 64), 256>>>(F + O_X1, 64, F + O_WD2, 128, F + O_A2, 128, 64, nullptr, nullptr);
    gemm_kernel<128, 128, 0><<<dim3(1, 64), 256>>>(F + O_X1, 64, We2 + 8192, 128, F + O_B2, 128, 64, nullptr, nullptr);
    gathermax_kernel<<<NPTS, 128>>>(F + O_A2, F + O_B2, idx, se2, be2, F + O_X2, 128);

    // --- graph_attn 1: D=256 ---
    gemm_kernel<128, 128, 0><<<dim3(2, 64), 256>>>(F + O_X2, 128, Wq1, 256, F + O_Q1, 256, 128, nullptr, nullptr);
    gemm_kernel<128, 128, 0><<<dim3(2, 64), 256>>>(F + O_X2, 128, Wk1, 256, F + O_K1, 256, 128, nullptr, nullptr);
    gemm_kernel<128, 128, 0><<<dim3(2, 64), 256>>>(F + O_X2, 128, Wv1, 256, F + O_V1, 256, 128, nullptr, nullptr);
    attn_kernel<256><<<NPTS, 256>>>(F + O_Q1, F + O_K1, F + O_V1, idx, sa1, ba1, F + O_X3);

    // --- graph_attn 2: D=512 ---
    gemm_kernel<128, 128, 0><<<dim3(4, 64), 256>>>(F + O_X3, 256, Wq2, 512, F + O_Q2, 512, 256, nullptr, nullptr);
    gemm_kernel<128, 128, 0><<<dim3(4, 64), 256>>>(F + O_X3, 256, Wk2, 512, F + O_K2, 512, 256, nullptr, nullptr);
    gemm_kernel<128, 128, 0><<<dim3(4, 64), 256>>>(F + O_X3, 256, Wv2, 512, F + O_V2, 512, 256, nullptr, nullptr);
    attn_kernel<512><<<NPTS, 512>>>(F + O_Q2, F + O_K2, F + O_V2, idx, sa2, ba2, F + O_X4);

    // --- downsample layer ---
    rows3_kernel<<<dim3(NPTS, 4), 128>>>(p4, 1, Wtd, F + O_PX, 512);
    gemm_kernel<128, 128, 1><<<dim3(4, 64), 256>>>(F + O_X4, 512, Wtd + 3 * 512, 512, F + O_PX, 512, 512, nullptr, nullptr);
    rows3_kernel<<<dim3(NDOWN, 4), 128>>>(p4, 4, Wtd, F + O_PM, 512);
    downgather_kernel<<<NDOWN, 512>>>(F + O_PX, F + O_PM, idxd, sd, bd, F + O_XD);

    // --- global mean folded into bias; xu = relu(xd@Wu1*su1 + beff) ---
    colsum_kernel<<<4, 128>>>(F + O_XD, F + O_GS);
    beff_kernel<<<1, 256>>>(F + O_GS, Wu2, su2, bu1, bu2, F + O_BE);
    gemm_kernel<64, 64, 2><<<dim3(4, 32), 256>>>(F + O_XD, 512, Wu1, 256, F + O_XU, 256, 512, su1, F + O_BE);

    // --- h = relu((xu@Wc1)*sc + (bc1*sc+bc)) ---
    b2eff_kernel<<<1, 128>>>(bc1, scv, bcv, F + O_B2E);
    gemm_kernel<64, 64, 2><<<dim3(2, 32), 256>>>(F + O_XU, 256, Wc1, 128, F + O_H, 128, 256, scv, F + O_B2E);

    // --- out = h@Wc2 + bc2 ---
    final_kernel<<<(NDOWN * 6 + 127) / 128, 128>>>(F + O_H, Wc2, bc2, (float*)d_out);
}